// round 9
// baseline (speedup 1.0000x reference)
#include <cuda_runtime.h>
#include <cuda_bf16.h>
#include <cstdint>

#define NN 131072
#define NE 262144
#define DD 128
#define LL 5

// ------------------------- scratch (device globals) ------------------------
__device__ float g_h0[(size_t)NN * DD];
__device__ float g_agg[(size_t)NN * DD];
__device__ float g_hm[(size_t)NN * DD];
__device__ uint32_t g_w1h[LL * 256 * 64];   // [l][n][k2] bf16x2 hi
__device__ uint32_t g_w1l[LL * 256 * 64];   // lo
__device__ uint32_t g_w2h[LL * 128 * 128];
__device__ uint32_t g_w2l[LL * 128 * 128];
__device__ double g_sumsd[256];             // [0:128) sum, [128:256) sumsq
__device__ float g_ss[256];                 // [0:128) scale, [128:256) shift
// CSR scratch
__device__ int g_deg[NN];
__device__ int g_rowptr[NN + 1];
__device__ int g_bsum[128];
__device__ int g_eperm[NE];                 // src | (combo<<17)

// ------------------------- helpers -----------------------------------------
__device__ __forceinline__ uint32_t sm2u(const void* p) {
    uint32_t a;
    asm("{ .reg .u64 t; cvta.to.shared.u64 t, %1; cvt.u32.u64 %0, t; }" : "=r"(a) : "l"(p));
    return a;
}
#define LDSM4(d0, d1, d2, d3, a) \
    asm volatile("ldmatrix.sync.aligned.m8n8.x4.shared.b16 {%0,%1,%2,%3}, [%4];" \
                 : "=r"(d0), "=r"(d1), "=r"(d2), "=r"(d3) : "r"(a))

__device__ __forceinline__ void split2(float v0, float v1, uint32_t& hi, uint32_t& lo) {
    __nv_bfloat16 h0 = __float2bfloat16_rn(v0), h1 = __float2bfloat16_rn(v1);
    __nv_bfloat162 hp; hp.x = h0; hp.y = h1;
    hi = *(uint32_t*)&hp;
    float l0 = v0 - __bfloat162float(h0), l1 = v1 - __bfloat162float(h1);
    __nv_bfloat162 lp = __floats2bfloat162_rn(l0, l1);
    lo = *(uint32_t*)&lp;
}
__device__ __forceinline__ void mma_bf16(float* d, const uint32_t* a, const uint32_t* b) {
    asm volatile(
        "mma.sync.aligned.m16n8k16.row.col.f32.bf16.bf16.f32 "
        "{%0,%1,%2,%3}, {%4,%5,%6,%7}, {%8,%9}, {%0,%1,%2,%3};"
        : "+f"(d[0]), "+f"(d[1]), "+f"(d[2]), "+f"(d[3])
        : "r"(a[0]), "r"(a[1]), "r"(a[2]), "r"(a[3]), "r"(b[0]), "r"(b[1]));
}

// ------------------------- weight prep --------------------------------------
__global__ void k_t1(const float* __restrict__ W1) {
    int i = blockIdx.x * 256 + threadIdx.x;
    int l = i / 16384, r = i - l * 16384;
    int n = r >> 6, k2 = r & 63;
    float w0 = W1[l * 32768 + (2 * k2) * 256 + n];
    float w1 = W1[l * 32768 + (2 * k2 + 1) * 256 + n];
    uint32_t hi, lo; split2(w0, w1, hi, lo);
    g_w1h[i] = hi; g_w1l[i] = lo;
}
__global__ void k_t2(const float* __restrict__ W2) {
    int i = blockIdx.x * 256 + threadIdx.x;
    int l = i / 16384, r = i - l * 16384;
    int n = r >> 7, k2 = r & 127;
    float w0 = W2[l * 32768 + (2 * k2) * 128 + n];
    float w1 = W2[l * 32768 + (2 * k2 + 1) * 128 + n];
    uint32_t hi, lo; split2(w0, w1, hi, lo);
    g_w2h[i] = hi; g_w2l[i] = lo;
}
__global__ void k_init(const int* __restrict__ x, const float* __restrict__ xe1, const float* __restrict__ xe2) {
    int t = blockIdx.x * 256 + threadIdx.x;
    int row = t >> 5, c4 = t & 31;
    int i0 = x[2 * row], i1 = x[2 * row + 1];
    float4 a = ((const float4*)xe1)[i0 * 32 + c4];
    float4 b = ((const float4*)xe2)[i1 * 32 + c4];
    ((float4*)g_h0)[t] = make_float4(a.x + b.x, a.y + b.y, a.z + b.z, a.w + b.w);
}

// ------------------------- CSR build ----------------------------------------
__global__ void k_ezero() { g_deg[blockIdx.x * 256 + threadIdx.x] = 0; }
__global__ void k_hist(const int* __restrict__ ei) {
    int e = blockIdx.x * 256 + threadIdx.x;
    atomicAdd(&g_deg[ei[NE + e]], 1);
}
__global__ void __launch_bounds__(1024) k_scan1() {
    __shared__ int s[1024];
    int t = threadIdx.x, i = blockIdx.x * 1024 + t;
    s[t] = g_deg[i];
    __syncthreads();
    #pragma unroll
    for (int off = 1; off < 1024; off <<= 1) {
        int x = (t >= off) ? s[t - off] : 0;
        __syncthreads();
        s[t] += x;
        __syncthreads();
    }
    g_rowptr[i + 1] = s[t];
    if (t == 1023) g_bsum[blockIdx.x] = s[1023];
}
__global__ void k_scan2() {
    __shared__ int s[128];
    int t = threadIdx.x;
    int v = g_bsum[t];
    s[t] = v;
    __syncthreads();
    #pragma unroll
    for (int off = 1; off < 128; off <<= 1) {
        int x = (t >= off) ? s[t - off] : 0;
        __syncthreads();
        s[t] += x;
        __syncthreads();
    }
    g_bsum[t] = s[t] - v;
}
__global__ void k_scan3() {
    int t = threadIdx.x, i = blockIdx.x * 256 + t;
    int base = g_bsum[i >> 10];
    int incl = g_rowptr[i + 1] + base;
    g_rowptr[i + 1] = incl;
    g_deg[i] = incl - g_deg[i];
    if (i == 0) g_rowptr[0] = 0;
}
__global__ void k_place(const int* __restrict__ ei, const int* __restrict__ ea) {
    int e = blockIdx.x * 256 + threadIdx.x;
    int dst = ei[NE + e];
    int src = ei[e];
    int combo = ea[2 * e] * 3 + ea[2 * e + 1];
    int pos = atomicAdd(&g_deg[dst], 1);
    g_eperm[pos] = src | (combo << 17);
}

// ------------------------- aggregation (warp per node) ----------------------
__global__ void __launch_bounds__(512) k_agg(
    int use_h0, const float* __restrict__ e1, const float* __restrict__ e2, int affine)
{
    __shared__ float4 comb[18 * 32];
    __shared__ float4 ssc[32], ssh[32];
    int tid = threadIdx.x;
    for (int i = tid; i < 18 * 32; i += 512) {
        int cb = i >> 5, c4 = i & 31;
        int a0 = cb / 3, a1 = cb - a0 * 3;
        float4 v1 = ((const float4*)e1)[a0 * 32 + c4];
        float4 v2 = ((const float4*)e2)[a1 * 32 + c4];
        comb[i] = make_float4(v1.x + v2.x, v1.y + v2.y, v1.z + v2.z, v1.w + v2.w);
    }
    if (tid < 32) {
        if (affine) {
            ssc[tid] = ((const float4*)g_ss)[tid];
            ssh[tid] = ((const float4*)g_ss)[32 + tid];
        } else {
            ssc[tid] = make_float4(1.f, 1.f, 1.f, 1.f);
            ssh[tid] = make_float4(0.f, 0.f, 0.f, 0.f);
        }
    }
    __syncthreads();
    if (blockIdx.x == 0 && tid < 128) {
        g_sumsd[2 * tid] = 0.0; g_sumsd[2 * tid + 1] = 0.0;
    }
    int lane = tid & 31;
    int node = blockIdx.x * 16 + (tid >> 5);
    const float4* src = (const float4*)(use_h0 ? g_h0 : g_hm);
    float4 s = ssc[lane], b = ssh[lane];
    float4 v = src[(size_t)node * 32 + lane];
    float4 acc;
    if (affine) {
        acc.x = fmaxf(fmaf(v.x, s.x, b.x), 0.f);
        acc.y = fmaxf(fmaf(v.y, s.y, b.y), 0.f);
        acc.z = fmaxf(fmaf(v.z, s.z, b.z), 0.f);
        acc.w = fmaxf(fmaf(v.w, s.w, b.w), 0.f);
    } else acc = v;
    float4 cm = comb[12 * 32 + lane];
    acc.x += cm.x; acc.y += cm.y; acc.z += cm.z; acc.w += cm.w;

    int beg = g_rowptr[node], end = g_rowptr[node + 1];
    int e = beg;
    for (; e + 1 < end; e += 2) {
        int p1 = g_eperm[e], p2 = g_eperm[e + 1];
        float4 u1 = src[(size_t)(p1 & 0x1FFFF) * 32 + lane];
        float4 u2 = src[(size_t)(p2 & 0x1FFFF) * 32 + lane];
        if (affine) {
            u1.x = fmaxf(fmaf(u1.x, s.x, b.x), 0.f); u1.y = fmaxf(fmaf(u1.y, s.y, b.y), 0.f);
            u1.z = fmaxf(fmaf(u1.z, s.z, b.z), 0.f); u1.w = fmaxf(fmaf(u1.w, s.w, b.w), 0.f);
            u2.x = fmaxf(fmaf(u2.x, s.x, b.x), 0.f); u2.y = fmaxf(fmaf(u2.y, s.y, b.y), 0.f);
            u2.z = fmaxf(fmaf(u2.z, s.z, b.z), 0.f); u2.w = fmaxf(fmaf(u2.w, s.w, b.w), 0.f);
        }
        float4 c1 = comb[(p1 >> 17) * 32 + lane];
        float4 c2 = comb[(p2 >> 17) * 32 + lane];
        acc.x += u1.x + c1.x + u2.x + c2.x;
        acc.y += u1.y + c1.y + u2.y + c2.y;
        acc.z += u1.z + c1.z + u2.z + c2.z;
        acc.w += u1.w + c1.w + u2.w + c2.w;
    }
    if (e < end) {
        int p = g_eperm[e];
        float4 u = src[(size_t)(p & 0x1FFFF) * 32 + lane];
        if (affine) {
            u.x = fmaxf(fmaf(u.x, s.x, b.x), 0.f); u.y = fmaxf(fmaf(u.y, s.y, b.y), 0.f);
            u.z = fmaxf(fmaf(u.z, s.z, b.z), 0.f); u.w = fmaxf(fmaf(u.w, s.w, b.w), 0.f);
        }
        float4 c = comb[(p >> 17) * 32 + lane];
        acc.x += u.x + c.x; acc.y += u.y + c.y;
        acc.z += u.z + c.z; acc.w += u.w + c.w;
    }
    ((float4*)g_agg)[(size_t)node * 32 + lane] = acc;
}

// ------------------------- BN stats / final ---------------------------------
__global__ void k_stats(const float* __restrict__ gamma, const float* __restrict__ beta) {
    int c = threadIdx.x;
    double mu  = g_sumsd[c] * (1.0 / NN);
    double var = g_sumsd[128 + c] * (1.0 / NN) - mu * mu;
    float sc = (float)(rsqrt(var + 1e-5) * (double)gamma[c]);
    g_ss[c] = sc;
    g_ss[128 + c] = (float)((double)beta[c] - mu * (double)sc);
}
__global__ void k_final(float* __restrict__ out) {
    int t = blockIdx.x * 256 + threadIdx.x;
    int c4 = t & 31;
    float4 v = ((const float4*)g_hm)[t];
    float4 s = ((const float4*)g_ss)[c4];
    float4 b = ((const float4*)g_ss)[32 + c4];
    ((float4*)out)[t] = make_float4(fmaf(v.x, s.x, b.x), fmaf(v.y, s.y, b.y),
                                    fmaf(v.z, s.z, b.z), fmaf(v.w, s.w, b.w));
}

// ------------------------- fused MLP (bf16x3, ldmatrix, prefetch) -----------
#define A2H_OFF 0           // 128 x 132 u32
#define A2L_OFF 67584
#define A2_S   132
#define ASH_OFF 135168      // 128 x 20 u32
#define ASL_OFF 145408
#define BSH_OFF 155648      // 256 x 20 u32
#define BSL_OFF 176128
#define SB_OFF  196608      // 384 floats
#define BND_OFF 198144      // 256 doubles
#define SM_TOT  200192

__global__ void __launch_bounds__(512, 1) k_gemm(
    int l, const float* __restrict__ b1p, const float* __restrict__ b2p)
{
    extern __shared__ char smem[];
    uint32_t* A2H = (uint32_t*)(smem + A2H_OFF);
    uint32_t* A2L = (uint32_t*)(smem + A2L_OFF);
    uint32_t* AsH = (uint32_t*)(smem + ASH_OFF);
    uint32_t* AsL = (uint32_t*)(smem + ASL_OFF);
    uint32_t* BsH = (uint32_t*)(smem + BSH_OFF);
    uint32_t* BsL = (uint32_t*)(smem + BSL_OFF);
    float*    sb  = (float*)(smem + SB_OFF);
    double*   bnd = (double*)(smem + BND_OFF);
    const int tid = threadIdx.x, w = tid >> 5, lane = tid & 31;
    const int g = lane >> 2, tig = lane & 3;
    const int wm = w & 3, wn = w >> 2;
    const uint32_t* w1h = g_w1h + l * 16384;
    const uint32_t* w1l = g_w1l + l * 16384;
    const uint32_t* w2h = g_w2h + l * 16384;
    const uint32_t* w2l = g_w2l + l * 16384;
    const size_t rowbase = (size_t)blockIdx.x * 128;

    if (tid < 384) sb[tid] = (tid < 256) ? b1p[tid] : b2p[tid - 256];
    if (tid < 256) bnd[tid] = 0.0;

    // smem u32 bases for ldmatrix
    const uint32_t asH = sm2u(AsH), asL = sm2u(AsL);
    const uint32_t bsH = sm2u(BsH), bsL = sm2u(BsL);
    const uint32_t a2h = sm2u(A2H), a2l = sm2u(A2L);
    // per-lane ldmatrix base offsets (bytes)
    const int lx = lane & 15, hx = lane >> 4;
    const int r7 = lane & 7, p8 = (lane >> 3) & 1, n8 = lane >> 4;
    const uint32_t offA  = ((wm * 32 + lx) * 20 + hx * 4) * 4;
    const uint32_t offA2 = ((wm * 32 + lx) * 132 + hx * 4) * 4;
    const uint32_t offB1 = ((wn * 64 + n8 * 8 + r7) * 20 + p8 * 4) * 4;
    const uint32_t offB2 = ((wn * 32 + n8 * 8 + r7) * 20 + p8 * 4) * 4;

    // ============ GEMM1: C1[128,256] = A[128,128] @ W1t^T ============
    float c1[2][8][4];
    #pragma unroll
    for (int mt = 0; mt < 2; mt++)
        #pragma unroll
        for (int nt = 0; nt < 8; nt++)
            #pragma unroll
            for (int q = 0; q < 4; q++) c1[mt][nt][q] = 0.f;

    const float2* ga2 = (const float2*)g_agg + rowbase * 64;
    float2 pa[4]; uint32_t pbh[8], pbl[8];
    #pragma unroll
    for (int it = 0; it < 4; it++) {                     // prefetch kc=0 A
        int i = it * 512 + tid, r = i >> 4, p = i & 15;
        pa[it] = ga2[r * 64 + p];
    }
    #pragma unroll
    for (int it = 0; it < 8; it++) {                     // prefetch kc=0 B1
        int i = it * 512 + tid, r = i >> 4, p = i & 15;
        pbh[it] = w1h[r * 64 + p]; pbl[it] = w1l[r * 64 + p];
    }
    for (int kc = 0; kc < 4; kc++) {
        #pragma unroll
        for (int it = 0; it < 4; it++) {                 // store A chunk
            int i = it * 512 + tid, r = i >> 4, p = i & 15;
            uint32_t hi, lo; split2(pa[it].x, pa[it].y, hi, lo);
            AsH[r * 20 + p] = hi; AsL[r * 20 + p] = lo;
        }
        #pragma unroll
        for (int it = 0; it < 8; it++) {                 // store B1 chunk
            int i = it * 512 + tid, r = i >> 4, p = i & 15;
            BsH[r * 20 + p] = pbh[it]; BsL[r * 20 + p] = pbl[it];
        }
        __syncthreads();
        if (kc < 3) {
            #pragma unroll
            for (int it = 0; it < 4; it++) {
                int i = it * 512 + tid, r = i >> 4, p = i & 15;
                pa[it] = ga2[r * 64 + (kc + 1) * 16 + p];
            }
            #pragma unroll
            for (int it = 0; it < 8; it++) {
                int i = it * 512 + tid, r = i >> 4, p = i & 15;
                pbh[it] = w1h[r * 64 + (kc + 1) * 16 + p];
                pbl[it] = w1l[r * 64 + (kc + 1) * 16 + p];
            }
        }
        #pragma unroll
        for (int ks = 0; ks < 2; ks++) {
            const uint32_t kb4 = ks * 32;
            uint32_t ah[2][4], al[2][4];
            LDSM4(ah[0][0], ah[0][1], ah[0][2], ah[0][3], asH + offA + kb4);
            LDSM4(ah[1][0], ah[1][1], ah[1][2], ah[1][3], asH + offA + 1280 + kb4);
            LDSM4(al[0][0], al[0][1], al[0][2], al[0][3], asL + offA + kb4);
            LDSM4(al[1][0], al[1][1], al[1][2], al[1][3], asL + offA + 1280 + kb4);
            #pragma unroll
            for (int np = 0; np < 4; np++) {
                uint32_t bh[4], bl[4];
                LDSM4(bh[0], bh[1], bh[2], bh[3], bsH + offB1 + np * 1280 + kb4);
                LDSM4(bl[0], bl[1], bl[2], bl[3], bsL + offB1 + np * 1280 + kb4);
                #pragma unroll
                for (int mt = 0; mt < 2; mt++) {
                    mma_bf16(c1[mt][2 * np],     ah[mt], bh);
                    mma_bf16(c1[mt][2 * np],     ah[mt], bl);
                    mma_bf16(c1[mt][2 * np],     al[mt], bh);
                    mma_bf16(c1[mt][2 * np + 1], ah[mt], bh + 2);
                    mma_bf16(c1[mt][2 * np + 1], ah[mt], bl + 2);
                    mma_bf16(c1[mt][2 * np + 1], al[mt], bh + 2);
                }
            }
        }
        __syncthreads();
    }
    // epilogue1: +b1, relu, split -> A2
    #pragma unroll
    for (int mt = 0; mt < 2; mt++) {
        int r0 = wm * 32 + mt * 16 + g;
        #pragma unroll
        for (int nt = 0; nt < 8; nt++) {
            int cp = wn * 32 + nt * 4 + tig;
            float v0 = fmaxf(c1[mt][nt][0] + sb[2 * cp], 0.f);
            float v1 = fmaxf(c1[mt][nt][1] + sb[2 * cp + 1], 0.f);
            float v2 = fmaxf(c1[mt][nt][2] + sb[2 * cp], 0.f);
            float v3 = fmaxf(c1[mt][nt][3] + sb[2 * cp + 1], 0.f);
            uint32_t hi, lo;
            split2(v0, v1, hi, lo);
            A2H[r0 * A2_S + cp] = hi; A2L[r0 * A2_S + cp] = lo;
            split2(v2, v3, hi, lo);
            A2H[(r0 + 8) * A2_S + cp] = hi; A2L[(r0 + 8) * A2_S + cp] = lo;
        }
    }
    __syncthreads();

    // ============ GEMM2: C2[128,128] = A2[128,256] @ W2t^T ============
    float c2[2][4][4];
    #pragma unroll
    for (int mt = 0; mt < 2; mt++)
        #pragma unroll
        for (int nt = 0; nt < 4; nt++)
            #pragma unroll
            for (int q = 0; q < 4; q++) c2[mt][nt][q] = 0.f;

    uint32_t qbh[4], qbl[4];
    #pragma unroll
    for (int it = 0; it < 4; it++) {                     // prefetch kc=0 B2
        int i = it * 512 + tid, r = i >> 4, p = i & 15;
        qbh[it] = w2h[r * 128 + p]; qbl[it] = w2l[r * 128 + p];
    }
    for (int kc = 0; kc < 8; kc++) {
        #pragma unroll
        for (int it = 0; it < 4; it++) {
            int i = it * 512 + tid, r = i >> 4, p = i & 15;
            AsH[r * 20 + p] = qbh[it]; AsL[r * 20 + p] = qbl[it];
        }
        __syncthreads();
        if (kc < 7) {
            #pragma unroll
            for (int it = 0; it < 4; it++) {
                int i = it * 512 + tid, r = i >> 4, p = i & 15;
                qbh[it] = w2h[r * 128 + (kc + 1) * 16 + p];
                qbl[it] = w2l[r * 128 + (kc + 1) * 16 + p];
            }
        }
        #pragma unroll
        for (int ks = 0; ks < 2; ks++) {
            const uint32_t kbA = (kc * 16 + ks * 8) * 4;   // A2 pair-bytes
            const uint32_t kb4 = ks * 32;                  // chunk pair-bytes
            uint32_t ah[2][4], al[2][4];
            LDSM4(ah[0][0], ah[0][1], ah[0][2], ah[0][3], a2h + offA2 + kbA);
            LDSM4(ah[1][0], ah[1][1], ah[1][2], ah[1][3], a2h + offA2 + 8448 + kbA);
            LDSM4(al[0][0], al[0][1], al[0][2], al[0][3], a2l + offA2 + kbA);
            LDSM4(al[1][0], al[1][1], al[1][2], al[1][3], a2l + offA2 + 8448 + kbA);
            #pragma unroll
            for (int np = 0; np < 2; np++) {
                uint32_t bh[4], bl[4];
                LDSM4(bh[0], bh[1], bh[2], bh[3], asH + offB2 + np * 1280 + kb4);
                LDSM4(bl[0], bl[1], bl[2], bl[3], asL + offB2 + np * 1280 + kb4);
                #pragma unroll
                for (int mt = 0; mt < 2; mt++) {
                    mma_bf16(c2[mt][2 * np],     ah[mt], bh);
                    mma_bf16(c2[mt][2 * np],     ah[mt], bl);
                    mma_bf16(c2[mt][2 * np],     al[mt], bh);
                    mma_bf16(c2[mt][2 * np + 1], ah[mt], bh + 2);
                    mma_bf16(c2[mt][2 * np + 1], ah[mt], bl + 2);
                    mma_bf16(c2[mt][2 * np + 1], al[mt], bh + 2);
                }
            }
        }
        __syncthreads();
    }

    // epilogue2: +b2 -> g_hm, BN partial sums (double)
    float* hm = g_hm + rowbase * DD;
    float sA[4][2], qA[4][2];
    #pragma unroll
    for (int nt = 0; nt < 4; nt++) { sA[nt][0] = sA[nt][1] = qA[nt][0] = qA[nt][1] = 0.f; }
    #pragma unroll
    for (int mt = 0; mt < 2; mt++) {
        int r0 = wm * 32 + mt * 16 + g;
        #pragma unroll
        for (int nt = 0; nt < 4; nt++) {
            int col = wn * 32 + nt * 8 + 2 * tig;
            float v00 = c2[mt][nt][0] + sb[256 + col];
            float v01 = c2[mt][nt][1] + sb[256 + col + 1];
            float v10 = c2[mt][nt][2] + sb[256 + col];
            float v11 = c2[mt][nt][3] + sb[256 + col + 1];
            *(float2*)&hm[r0 * DD + col] = make_float2(v00, v01);
            *(float2*)&hm[(r0 + 8) * DD + col] = make_float2(v10, v11);
            sA[nt][0] += v00 + v10; qA[nt][0] += v00 * v00 + v10 * v10;
            sA[nt][1] += v01 + v11; qA[nt][1] += v01 * v01 + v11 * v11;
        }
    }
    #pragma unroll
    for (int nt = 0; nt < 4; nt++)
        #pragma unroll
        for (int p = 0; p < 2; p++) {
            float s = sA[nt][p], q = qA[nt][p];
            #pragma unroll
            for (int o = 16; o >= 4; o >>= 1) {
                s += __shfl_xor_sync(0xFFFFFFFFu, s, o);
                q += __shfl_xor_sync(0xFFFFFFFFu, q, o);
            }
            if (g == 0) {
                int col = wn * 32 + nt * 8 + 2 * tig + p;
                atomicAdd(&bnd[col], (double)s);
                atomicAdd(&bnd[128 + col], (double)q);
            }
        }
    __syncthreads();
    if (tid < 256) atomicAdd(&g_sumsd[tid], bnd[tid]);
}

// ------------------------- launch -------------------------------------------
extern "C" void kernel_launch(void* const* d_in, const int* in_sizes, int n_in,
                              void* d_out, int out_size) {
    const int*   x    = (const int*)d_in[0];
    const int*   ei   = (const int*)d_in[1];
    const int*   ea   = (const int*)d_in[2];
    const float* xe1  = (const float*)d_in[3];
    const float* xe2  = (const float*)d_in[4];
    const float* ee1  = (const float*)d_in[5];
    const float* ee2  = (const float*)d_in[6];
    const float* W1   = (const float*)d_in[7];
    const float* b1   = (const float*)d_in[8];
    const float* W2   = (const float*)d_in[9];
    const float* b2   = (const float*)d_in[10];
    const float* gam  = (const float*)d_in[11];
    const float* bet  = (const float*)d_in[12];
    float* out = (float*)d_out;

    cudaFuncSetAttribute(k_gemm, cudaFuncAttributeMaxDynamicSharedMemorySize, SM_TOT);

    k_t1<<<320, 256>>>(W1);
    k_t2<<<320, 256>>>(W2);
    k_init<<<16384, 256>>>(x, xe1, xe2);
    // CSR build
    k_ezero<<<512, 256>>>();
    k_hist<<<1024, 256>>>(ei);
    k_scan1<<<128, 1024>>>();
    k_scan2<<<1, 128>>>();
    k_scan3<<<512, 256>>>();
    k_place<<<1024, 256>>>(ei, ea);
    for (int l = 0; l < LL; l++) {
        k_agg<<<8192, 512>>>(l == 0 ? 1 : 0,
                             ee1 + (size_t)l * 6 * DD, ee2 + (size_t)l * 3 * DD,
                             l > 0 ? 1 : 0);
        k_gemm<<<1024, 512, SM_TOT>>>(l, b1 + l * 256, b2 + l * 128);
        k_stats<<<1, 128>>>(gam + l * DD, bet + l * DD);
    }
    k_final<<<16384, 256>>>(out);
}

// round 10
// speedup vs baseline: 1.0015x; 1.0015x over previous
#include <cuda_runtime.h>
#include <cuda_bf16.h>
#include <cstdint>

#define NN 131072
#define NE 262144
#define DD 128
#define LL 5

// ------------------------- scratch (device globals) ------------------------
__device__ float g_h0[(size_t)NN * DD];
__device__ float g_agg[(size_t)NN * DD];
__device__ float g_hm[(size_t)NN * DD];
__device__ uint32_t g_w1h[LL * 256 * 64];   // [l][n][k2] bf16x2 hi
__device__ uint32_t g_w1l[LL * 256 * 64];   // lo
__device__ uint32_t g_w2h[LL * 128 * 128];
__device__ uint32_t g_w2l[LL * 128 * 128];
__device__ double g_sumsd[256];             // [0:128) sum, [128:256) sumsq
__device__ float g_ss[256];                 // [0:128) scale, [128:256) shift
// CSR scratch
__device__ int g_deg[NN];
__device__ int g_rowptr[NN + 1];
__device__ int g_bsum[128];
__device__ int g_eperm[NE];                 // src | (combo<<17)

// ------------------------- helpers -----------------------------------------
__device__ __forceinline__ uint32_t sm2u(const void* p) {
    uint32_t a;
    asm("{ .reg .u64 t; cvta.to.shared.u64 t, %1; cvt.u32.u64 %0, t; }" : "=r"(a) : "l"(p));
    return a;
}
#define LDSM4(d0, d1, d2, d3, a) \
    asm volatile("ldmatrix.sync.aligned.m8n8.x4.shared.b16 {%0,%1,%2,%3}, [%4];" \
                 : "=r"(d0), "=r"(d1), "=r"(d2), "=r"(d3) : "r"(a))

__device__ __forceinline__ void split2(float v0, float v1, uint32_t& hi, uint32_t& lo) {
    __nv_bfloat16 h0 = __float2bfloat16_rn(v0), h1 = __float2bfloat16_rn(v1);
    __nv_bfloat162 hp; hp.x = h0; hp.y = h1;
    hi = *(uint32_t*)&hp;
    float l0 = v0 - __bfloat162float(h0), l1 = v1 - __bfloat162float(h1);
    __nv_bfloat162 lp = __floats2bfloat162_rn(l0, l1);
    lo = *(uint32_t*)&lp;
}
__device__ __forceinline__ void mma_bf16(float* d, const uint32_t* a, const uint32_t* b) {
    asm volatile(
        "mma.sync.aligned.m16n8k16.row.col.f32.bf16.bf16.f32 "
        "{%0,%1,%2,%3}, {%4,%5,%6,%7}, {%8,%9}, {%0,%1,%2,%3};"
        : "+f"(d[0]), "+f"(d[1]), "+f"(d[2]), "+f"(d[3])
        : "r"(a[0]), "r"(a[1]), "r"(a[2]), "r"(a[3]), "r"(b[0]), "r"(b[1]));
}

// ------------------------- weight prep --------------------------------------
__global__ void k_t1(const float* __restrict__ W1) {
    int i = blockIdx.x * 256 + threadIdx.x;
    int l = i / 16384, r = i - l * 16384;
    int n = r >> 6, k2 = r & 63;
    float w0 = W1[l * 32768 + (2 * k2) * 256 + n];
    float w1 = W1[l * 32768 + (2 * k2 + 1) * 256 + n];
    uint32_t hi, lo; split2(w0, w1, hi, lo);
    g_w1h[i] = hi; g_w1l[i] = lo;
}
__global__ void k_t2(const float* __restrict__ W2) {
    int i = blockIdx.x * 256 + threadIdx.x;
    int l = i / 16384, r = i - l * 16384;
    int n = r >> 7, k2 = r & 127;
    float w0 = W2[l * 32768 + (2 * k2) * 128 + n];
    float w1 = W2[l * 32768 + (2 * k2 + 1) * 128 + n];
    uint32_t hi, lo; split2(w0, w1, hi, lo);
    g_w2h[i] = hi; g_w2l[i] = lo;
}
__global__ void k_init(const int* __restrict__ x, const float* __restrict__ xe1, const float* __restrict__ xe2) {
    int t = blockIdx.x * 256 + threadIdx.x;
    int row = t >> 5, c4 = t & 31;
    int i0 = x[2 * row], i1 = x[2 * row + 1];
    float4 a = ((const float4*)xe1)[i0 * 32 + c4];
    float4 b = ((const float4*)xe2)[i1 * 32 + c4];
    ((float4*)g_h0)[t] = make_float4(a.x + b.x, a.y + b.y, a.z + b.z, a.w + b.w);
}

// ------------------------- CSR build ----------------------------------------
__global__ void k_ezero() { g_deg[blockIdx.x * 256 + threadIdx.x] = 0; }
__global__ void k_hist(const int* __restrict__ ei) {
    int e = blockIdx.x * 256 + threadIdx.x;
    atomicAdd(&g_deg[ei[NE + e]], 1);
}
__global__ void __launch_bounds__(1024) k_scan1() {
    __shared__ int s[1024];
    int t = threadIdx.x, i = blockIdx.x * 1024 + t;
    s[t] = g_deg[i];
    __syncthreads();
    #pragma unroll
    for (int off = 1; off < 1024; off <<= 1) {
        int x = (t >= off) ? s[t - off] : 0;
        __syncthreads();
        s[t] += x;
        __syncthreads();
    }
    g_rowptr[i + 1] = s[t];
    if (t == 1023) g_bsum[blockIdx.x] = s[1023];
}
__global__ void k_scan2() {
    __shared__ int s[128];
    int t = threadIdx.x;
    int v = g_bsum[t];
    s[t] = v;
    __syncthreads();
    #pragma unroll
    for (int off = 1; off < 128; off <<= 1) {
        int x = (t >= off) ? s[t - off] : 0;
        __syncthreads();
        s[t] += x;
        __syncthreads();
    }
    g_bsum[t] = s[t] - v;
}
__global__ void k_scan3() {
    int t = threadIdx.x, i = blockIdx.x * 256 + t;
    int base = g_bsum[i >> 10];
    int incl = g_rowptr[i + 1] + base;
    g_rowptr[i + 1] = incl;
    g_deg[i] = incl - g_deg[i];
    if (i == 0) g_rowptr[0] = 0;
}
__global__ void k_place(const int* __restrict__ ei, const int* __restrict__ ea) {
    int e = blockIdx.x * 256 + threadIdx.x;
    int dst = ei[NE + e];
    int src = ei[e];
    int combo = ea[2 * e] * 3 + ea[2 * e + 1];
    int pos = atomicAdd(&g_deg[dst], 1);
    g_eperm[pos] = src | (combo << 17);
}

// ------------------------- aggregation (warp per node) ----------------------
__global__ void __launch_bounds__(512) k_agg(
    int use_h0, const float* __restrict__ e1, const float* __restrict__ e2, int affine)
{
    __shared__ float4 comb[18 * 32];
    __shared__ float4 ssc[32], ssh[32];
    int tid = threadIdx.x;
    for (int i = tid; i < 18 * 32; i += 512) {
        int cb = i >> 5, c4 = i & 31;
        int a0 = cb / 3, a1 = cb - a0 * 3;
        float4 v1 = ((const float4*)e1)[a0 * 32 + c4];
        float4 v2 = ((const float4*)e2)[a1 * 32 + c4];
        comb[i] = make_float4(v1.x + v2.x, v1.y + v2.y, v1.z + v2.z, v1.w + v2.w);
    }
    if (tid < 32) {
        if (affine) {
            ssc[tid] = ((const float4*)g_ss)[tid];
            ssh[tid] = ((const float4*)g_ss)[32 + tid];
        } else {
            ssc[tid] = make_float4(1.f, 1.f, 1.f, 1.f);
            ssh[tid] = make_float4(0.f, 0.f, 0.f, 0.f);
        }
    }
    __syncthreads();
    if (blockIdx.x == 0 && tid < 128) {
        g_sumsd[2 * tid] = 0.0; g_sumsd[2 * tid + 1] = 0.0;
    }
    int lane = tid & 31;
    int node = blockIdx.x * 16 + (tid >> 5);
    const float4* src = (const float4*)(use_h0 ? g_h0 : g_hm);
    float4 s = ssc[lane], b = ssh[lane];
    float4 v = src[(size_t)node * 32 + lane];
    float4 acc;
    if (affine) {
        acc.x = fmaxf(fmaf(v.x, s.x, b.x), 0.f);
        acc.y = fmaxf(fmaf(v.y, s.y, b.y), 0.f);
        acc.z = fmaxf(fmaf(v.z, s.z, b.z), 0.f);
        acc.w = fmaxf(fmaf(v.w, s.w, b.w), 0.f);
    } else acc = v;
    float4 cm = comb[12 * 32 + lane];
    acc.x += cm.x; acc.y += cm.y; acc.z += cm.z; acc.w += cm.w;

    int beg = g_rowptr[node], end = g_rowptr[node + 1];
    int e = beg;
    for (; e + 1 < end; e += 2) {
        int p1 = g_eperm[e], p2 = g_eperm[e + 1];
        float4 u1 = src[(size_t)(p1 & 0x1FFFF) * 32 + lane];
        float4 u2 = src[(size_t)(p2 & 0x1FFFF) * 32 + lane];
        if (affine) {
            u1.x = fmaxf(fmaf(u1.x, s.x, b.x), 0.f); u1.y = fmaxf(fmaf(u1.y, s.y, b.y), 0.f);
            u1.z = fmaxf(fmaf(u1.z, s.z, b.z), 0.f); u1.w = fmaxf(fmaf(u1.w, s.w, b.w), 0.f);
            u2.x = fmaxf(fmaf(u2.x, s.x, b.x), 0.f); u2.y = fmaxf(fmaf(u2.y, s.y, b.y), 0.f);
            u2.z = fmaxf(fmaf(u2.z, s.z, b.z), 0.f); u2.w = fmaxf(fmaf(u2.w, s.w, b.w), 0.f);
        }
        float4 c1 = comb[(p1 >> 17) * 32 + lane];
        float4 c2 = comb[(p2 >> 17) * 32 + lane];
        acc.x += u1.x + c1.x + u2.x + c2.x;
        acc.y += u1.y + c1.y + u2.y + c2.y;
        acc.z += u1.z + c1.z + u2.z + c2.z;
        acc.w += u1.w + c1.w + u2.w + c2.w;
    }
    if (e < end) {
        int p = g_eperm[e];
        float4 u = src[(size_t)(p & 0x1FFFF) * 32 + lane];
        if (affine) {
            u.x = fmaxf(fmaf(u.x, s.x, b.x), 0.f); u.y = fmaxf(fmaf(u.y, s.y, b.y), 0.f);
            u.z = fmaxf(fmaf(u.z, s.z, b.z), 0.f); u.w = fmaxf(fmaf(u.w, s.w, b.w), 0.f);
        }
        float4 c = comb[(p >> 17) * 32 + lane];
        acc.x += u.x + c.x; acc.y += u.y + c.y;
        acc.z += u.z + c.z; acc.w += u.w + c.w;
    }
    ((float4*)g_agg)[(size_t)node * 32 + lane] = acc;
}

// ------------------------- BN stats / final ---------------------------------
__global__ void k_stats(const float* __restrict__ gamma, const float* __restrict__ beta) {
    int c = threadIdx.x;
    double mu  = g_sumsd[c] * (1.0 / NN);
    double var = g_sumsd[128 + c] * (1.0 / NN) - mu * mu;
    float sc = (float)(rsqrt(var + 1e-5) * (double)gamma[c]);
    g_ss[c] = sc;
    g_ss[128 + c] = (float)((double)beta[c] - mu * (double)sc);
}
__global__ void k_final(float* __restrict__ out) {
    int t = blockIdx.x * 256 + threadIdx.x;
    int c4 = t & 31;
    float4 v = ((const float4*)g_hm)[t];
    float4 s = ((const float4*)g_ss)[c4];
    float4 b = ((const float4*)g_ss)[32 + c4];
    ((float4*)out)[t] = make_float4(fmaf(v.x, s.x, b.x), fmaf(v.y, s.y, b.y),
                                    fmaf(v.z, s.z, b.z), fmaf(v.w, s.w, b.w));
}

// ------------------------- fused MLP (bf16x3, ldmatrix, prefetch) -----------
#define A2H_OFF 0           // 128 x 132 u32
#define A2L_OFF 67584
#define A2_S   132
#define ASH_OFF 135168      // 128 x 20 u32
#define ASL_OFF 145408
#define BSH_OFF 155648      // 256 x 20 u32
#define BSL_OFF 176128
#define SB_OFF  196608      // 384 floats
#define BND_OFF 198144      // 256 doubles
#define SM_TOT  200192

__global__ void __launch_bounds__(512, 1) k_gemm(
    int l, const float* __restrict__ b1p, const float* __restrict__ b2p)
{
    extern __shared__ char smem[];
    uint32_t* A2H = (uint32_t*)(smem + A2H_OFF);
    uint32_t* A2L = (uint32_t*)(smem + A2L_OFF);
    uint32_t* AsH = (uint32_t*)(smem + ASH_OFF);
    uint32_t* AsL = (uint32_t*)(smem + ASL_OFF);
    uint32_t* BsH = (uint32_t*)(smem + BSH_OFF);
    uint32_t* BsL = (uint32_t*)(smem + BSL_OFF);
    float*    sb  = (float*)(smem + SB_OFF);
    double*   bnd = (double*)(smem + BND_OFF);
    const int tid = threadIdx.x, w = tid >> 5, lane = tid & 31;
    const int g = lane >> 2, tig = lane & 3;
    const int wm = w & 3, wn = w >> 2;
    const uint32_t* w1h = g_w1h + l * 16384;
    const uint32_t* w1l = g_w1l + l * 16384;
    const uint32_t* w2h = g_w2h + l * 16384;
    const uint32_t* w2l = g_w2l + l * 16384;
    const size_t rowbase = (size_t)blockIdx.x * 128;

    if (tid < 384) sb[tid] = (tid < 256) ? b1p[tid] : b2p[tid - 256];
    if (tid < 256) bnd[tid] = 0.0;

    // smem u32 bases for ldmatrix
    const uint32_t asH = sm2u(AsH), asL = sm2u(AsL);
    const uint32_t bsH = sm2u(BsH), bsL = sm2u(BsL);
    const uint32_t a2h = sm2u(A2H), a2l = sm2u(A2L);
    // per-lane ldmatrix base offsets (bytes)
    const int lx = lane & 15, hx = lane >> 4;
    const int r7 = lane & 7, p8 = (lane >> 3) & 1, n8 = lane >> 4;
    const uint32_t offA  = ((wm * 32 + lx) * 20 + hx * 4) * 4;
    const uint32_t offA2 = ((wm * 32 + lx) * 132 + hx * 4) * 4;
    const uint32_t offB1 = ((wn * 64 + n8 * 8 + r7) * 20 + p8 * 4) * 4;
    const uint32_t offB2 = ((wn * 32 + n8 * 8 + r7) * 20 + p8 * 4) * 4;

    // ============ GEMM1: C1[128,256] = A[128,128] @ W1t^T ============
    float c1[2][8][4];
    #pragma unroll
    for (int mt = 0; mt < 2; mt++)
        #pragma unroll
        for (int nt = 0; nt < 8; nt++)
            #pragma unroll
            for (int q = 0; q < 4; q++) c1[mt][nt][q] = 0.f;

    const float2* ga2 = (const float2*)g_agg + rowbase * 64;
    float2 pa[4]; uint32_t pbh[8], pbl[8];
    #pragma unroll
    for (int it = 0; it < 4; it++) {                     // prefetch kc=0 A
        int i = it * 512 + tid, r = i >> 4, p = i & 15;
        pa[it] = ga2[r * 64 + p];
    }
    #pragma unroll
    for (int it = 0; it < 8; it++) {                     // prefetch kc=0 B1
        int i = it * 512 + tid, r = i >> 4, p = i & 15;
        pbh[it] = w1h[r * 64 + p]; pbl[it] = w1l[r * 64 + p];
    }
    for (int kc = 0; kc < 4; kc++) {
        #pragma unroll
        for (int it = 0; it < 4; it++) {                 // store A chunk
            int i = it * 512 + tid, r = i >> 4, p = i & 15;
            uint32_t hi, lo; split2(pa[it].x, pa[it].y, hi, lo);
            AsH[r * 20 + p] = hi; AsL[r * 20 + p] = lo;
        }
        #pragma unroll
        for (int it = 0; it < 8; it++) {                 // store B1 chunk
            int i = it * 512 + tid, r = i >> 4, p = i & 15;
            BsH[r * 20 + p] = pbh[it]; BsL[r * 20 + p] = pbl[it];
        }
        __syncthreads();
        if (kc < 3) {
            #pragma unroll
            for (int it = 0; it < 4; it++) {
                int i = it * 512 + tid, r = i >> 4, p = i & 15;
                pa[it] = ga2[r * 64 + (kc + 1) * 16 + p];
            }
            #pragma unroll
            for (int it = 0; it < 8; it++) {
                int i = it * 512 + tid, r = i >> 4, p = i & 15;
                pbh[it] = w1h[r * 64 + (kc + 1) * 16 + p];
                pbl[it] = w1l[r * 64 + (kc + 1) * 16 + p];
            }
        }
        #pragma unroll
        for (int ks = 0; ks < 2; ks++) {
            const uint32_t kb4 = ks * 32;
            uint32_t ah[2][4], al[2][4];
            LDSM4(ah[0][0], ah[0][1], ah[0][2], ah[0][3], asH + offA + kb4);
            LDSM4(ah[1][0], ah[1][1], ah[1][2], ah[1][3], asH + offA + 1280 + kb4);
            LDSM4(al[0][0], al[0][1], al[0][2], al[0][3], asL + offA + kb4);
            LDSM4(al[1][0], al[1][1], al[1][2], al[1][3], asL + offA + 1280 + kb4);
            #pragma unroll
            for (int np = 0; np < 4; np++) {
                uint32_t bh[4], bl[4];
                LDSM4(bh[0], bh[1], bh[2], bh[3], bsH + offB1 + np * 1280 + kb4);
                LDSM4(bl[0], bl[1], bl[2], bl[3], bsL + offB1 + np * 1280 + kb4);
                #pragma unroll
                for (int mt = 0; mt < 2; mt++) {
                    mma_bf16(c1[mt][2 * np],     ah[mt], bh);
                    mma_bf16(c1[mt][2 * np],     ah[mt], bl);
                    mma_bf16(c1[mt][2 * np],     al[mt], bh);
                    mma_bf16(c1[mt][2 * np + 1], ah[mt], bh + 2);
                    mma_bf16(c1[mt][2 * np + 1], ah[mt], bl + 2);
                    mma_bf16(c1[mt][2 * np + 1], al[mt], bh + 2);
                }
            }
        }
        __syncthreads();
    }
    // epilogue1: +b1, relu, split -> A2
    #pragma unroll
    for (int mt = 0; mt < 2; mt++) {
        int r0 = wm * 32 + mt * 16 + g;
        #pragma unroll
        for (int nt = 0; nt < 8; nt++) {
            int cp = wn * 32 + nt * 4 + tig;
            float v0 = fmaxf(c1[mt][nt][0] + sb[2 * cp], 0.f);
            float v1 = fmaxf(c1[mt][nt][1] + sb[2 * cp + 1], 0.f);
            float v2 = fmaxf(c1[mt][nt][2] + sb[2 * cp], 0.f);
            float v3 = fmaxf(c1[mt][nt][3] + sb[2 * cp + 1], 0.f);
            uint32_t hi, lo;
            split2(v0, v1, hi, lo);
            A2H[r0 * A2_S + cp] = hi; A2L[r0 * A2_S + cp] = lo;
            split2(v2, v3, hi, lo);
            A2H[(r0 + 8) * A2_S + cp] = hi; A2L[(r0 + 8) * A2_S + cp] = lo;
        }
    }
    __syncthreads();

    // ============ GEMM2: C2[128,128] = A2[128,256] @ W2t^T ============
    float c2[2][4][4];
    #pragma unroll
    for (int mt = 0; mt < 2; mt++)
        #pragma unroll
        for (int nt = 0; nt < 4; nt++)
            #pragma unroll
            for (int q = 0; q < 4; q++) c2[mt][nt][q] = 0.f;

    uint32_t qbh[4], qbl[4];
    #pragma unroll
    for (int it = 0; it < 4; it++) {                     // prefetch kc=0 B2
        int i = it * 512 + tid, r = i >> 4, p = i & 15;
        qbh[it] = w2h[r * 128 + p]; qbl[it] = w2l[r * 128 + p];
    }
    for (int kc = 0; kc < 8; kc++) {
        #pragma unroll
        for (int it = 0; it < 4; it++) {
            int i = it * 512 + tid, r = i >> 4, p = i & 15;
            AsH[r * 20 + p] = qbh[it]; AsL[r * 20 + p] = qbl[it];
        }
        __syncthreads();
        if (kc < 7) {
            #pragma unroll
            for (int it = 0; it < 4; it++) {
                int i = it * 512 + tid, r = i >> 4, p = i & 15;
                qbh[it] = w2h[r * 128 + (kc + 1) * 16 + p];
                qbl[it] = w2l[r * 128 + (kc + 1) * 16 + p];
            }
        }
        #pragma unroll
        for (int ks = 0; ks < 2; ks++) {
            const uint32_t kbA = (kc * 16 + ks * 8) * 4;   // A2 pair-bytes
            const uint32_t kb4 = ks * 32;                  // chunk pair-bytes
            uint32_t ah[2][4], al[2][4];
            LDSM4(ah[0][0], ah[0][1], ah[0][2], ah[0][3], a2h + offA2 + kbA);
            LDSM4(ah[1][0], ah[1][1], ah[1][2], ah[1][3], a2h + offA2 + 8448 + kbA);
            LDSM4(al[0][0], al[0][1], al[0][2], al[0][3], a2l + offA2 + kbA);
            LDSM4(al[1][0], al[1][1], al[1][2], al[1][3], a2l + offA2 + 8448 + kbA);
            #pragma unroll
            for (int np = 0; np < 2; np++) {
                uint32_t bh[4], bl[4];
                LDSM4(bh[0], bh[1], bh[2], bh[3], asH + offB2 + np * 1280 + kb4);
                LDSM4(bl[0], bl[1], bl[2], bl[3], asL + offB2 + np * 1280 + kb4);
                #pragma unroll
                for (int mt = 0; mt < 2; mt++) {
                    mma_bf16(c2[mt][2 * np],     ah[mt], bh);
                    mma_bf16(c2[mt][2 * np],     ah[mt], bl);
                    mma_bf16(c2[mt][2 * np],     al[mt], bh);
                    mma_bf16(c2[mt][2 * np + 1], ah[mt], bh + 2);
                    mma_bf16(c2[mt][2 * np + 1], ah[mt], bl + 2);
                    mma_bf16(c2[mt][2 * np + 1], al[mt], bh + 2);
                }
            }
        }
        __syncthreads();
    }

    // epilogue2: +b2 -> g_hm, BN partial sums (double)
    float* hm = g_hm + rowbase * DD;
    float sA[4][2], qA[4][2];
    #pragma unroll
    for (int nt = 0; nt < 4; nt++) { sA[nt][0] = sA[nt][1] = qA[nt][0] = qA[nt][1] = 0.f; }
    #pragma unroll
    for (int mt = 0; mt < 2; mt++) {
        int r0 = wm * 32 + mt * 16 + g;
        #pragma unroll
        for (int nt = 0; nt < 4; nt++) {
            int col = wn * 32 + nt * 8 + 2 * tig;
            float v00 = c2[mt][nt][0] + sb[256 + col];
            float v01 = c2[mt][nt][1] + sb[256 + col + 1];
            float v10 = c2[mt][nt][2] + sb[256 + col];
            float v11 = c2[mt][nt][3] + sb[256 + col + 1];
            *(float2*)&hm[r0 * DD + col] = make_float2(v00, v01);
            *(float2*)&hm[(r0 + 8) * DD + col] = make_float2(v10, v11);
            sA[nt][0] += v00 + v10; qA[nt][0] += v00 * v00 + v10 * v10;
            sA[nt][1] += v01 + v11; qA[nt][1] += v01 * v01 + v11 * v11;
        }
    }
    #pragma unroll
    for (int nt = 0; nt < 4; nt++)
        #pragma unroll
        for (int p = 0; p < 2; p++) {
            float s = sA[nt][p], q = qA[nt][p];
            #pragma unroll
            for (int o = 16; o >= 4; o >>= 1) {
                s += __shfl_xor_sync(0xFFFFFFFFu, s, o);
                q += __shfl_xor_sync(0xFFFFFFFFu, q, o);
            }
            if (g == 0) {
                int col = wn * 32 + nt * 8 + 2 * tig + p;
                atomicAdd(&bnd[col], (double)s);
                atomicAdd(&bnd[128 + col], (double)q);
            }
        }
    __syncthreads();
    if (tid < 256) atomicAdd(&g_sumsd[tid], bnd[tid]);
}

// ------------------------- launch -------------------------------------------
extern "C" void kernel_launch(void* const* d_in, const int* in_sizes, int n_in,
                              void* d_out, int out_size) {
    const int*   x    = (const int*)d_in[0];
    const int*   ei   = (const int*)d_in[1];
    const int*   ea   = (const int*)d_in[2];
    const float* xe1  = (const float*)d_in[3];
    const float* xe2  = (const float*)d_in[4];
    const float* ee1  = (const float*)d_in[5];
    const float* ee2  = (const float*)d_in[6];
    const float* W1   = (const float*)d_in[7];
    const float* b1   = (const float*)d_in[8];
    const float* W2   = (const float*)d_in[9];
    const float* b2   = (const float*)d_in[10];
    const float* gam  = (const float*)d_in[11];
    const float* bet  = (const float*)d_in[12];
    float* out = (float*)d_out;

    cudaFuncSetAttribute(k_gemm, cudaFuncAttributeMaxDynamicSharedMemorySize, SM_TOT);

    k_t1<<<320, 256>>>(W1);
    k_t2<<<320, 256>>>(W2);
    k_init<<<16384, 256>>>(x, xe1, xe2);
    // CSR build
    k_ezero<<<512, 256>>>();
    k_hist<<<1024, 256>>>(ei);
    k_scan1<<<128, 1024>>>();
    k_scan2<<<1, 128>>>();
    k_scan3<<<512, 256>>>();
    k_place<<<1024, 256>>>(ei, ea);
    for (int l = 0; l < LL; l++) {
        k_agg<<<8192, 512>>>(l == 0 ? 1 : 0,
                             ee1 + (size_t)l * 6 * DD, ee2 + (size_t)l * 3 * DD,
                             l > 0 ? 1 : 0);
        k_gemm<<<1024, 512, SM_TOT>>>(l, b1 + l * 256, b2 + l * 128);
        k_stats<<<1, 128>>>(gam + l * DD, bet + l * DD);
    }
    k_final<<<16384, 256>>>(out);
}

// round 11
// speedup vs baseline: 1.0439x; 1.0424x over previous
#include <cuda_runtime.h>
#include <cuda_bf16.h>
#include <cstdint>

#define NN 131072
#define NE 262144
#define DD 128
#define LL 5

// ------------------------- scratch (device globals) ------------------------
__device__ float g_h0[(size_t)NN * DD];
__device__ float g_bufA[(size_t)NN * DD];
__device__ float g_bufB[(size_t)NN * DD];
__device__ uint32_t g_w1h[LL * 256 * 64];   // [l][n][k2] bf16x2 hi
__device__ uint32_t g_w1l[LL * 256 * 64];
__device__ uint32_t g_w2h[LL * 128 * 128];
__device__ uint32_t g_w2l[LL * 128 * 128];
__device__ double g_sumsd[256];
__device__ float g_ss[256];
// CSR scratch
__device__ int g_deg[NN];
__device__ int g_rowptr[NN + 1];
__device__ int g_bsum[128];
__device__ int g_eperm[NE];                 // src | (combo<<17)

// ------------------------- helpers -----------------------------------------
__device__ __forceinline__ uint32_t sm2u(const void* p) {
    uint32_t a;
    asm("{ .reg .u64 t; cvta.to.shared.u64 t, %1; cvt.u32.u64 %0, t; }" : "=r"(a) : "l"(p));
    return a;
}
#define LDSM4(d0, d1, d2, d3, a) \
    asm volatile("ldmatrix.sync.aligned.m8n8.x4.shared.b16 {%0,%1,%2,%3}, [%4];" \
                 : "=r"(d0), "=r"(d1), "=r"(d2), "=r"(d3) : "r"(a))
#define CPASYNC16(dst, src) \
    asm volatile("cp.async.cg.shared.global [%0], [%1], 16;" :: "r"(dst), "l"(src) : "memory")
#define CPCOMMIT() asm volatile("cp.async.commit_group;" ::: "memory")
#define CPWAIT0()  asm volatile("cp.async.wait_group 0;" ::: "memory")

__device__ __forceinline__ void split2(float v0, float v1, uint32_t& hi, uint32_t& lo) {
    __nv_bfloat16 h0 = __float2bfloat16_rn(v0), h1 = __float2bfloat16_rn(v1);
    __nv_bfloat162 hp; hp.x = h0; hp.y = h1;
    hi = *(uint32_t*)&hp;
    float l0 = v0 - __bfloat162float(h0), l1 = v1 - __bfloat162float(h1);
    __nv_bfloat162 lp = __floats2bfloat162_rn(l0, l1);
    lo = *(uint32_t*)&lp;
}
__device__ __forceinline__ void mma_bf16(float* d, const uint32_t* a, const uint32_t* b) {
    asm volatile(
        "mma.sync.aligned.m16n8k16.row.col.f32.bf16.bf16.f32 "
        "{%0,%1,%2,%3}, {%4,%5,%6,%7}, {%8,%9}, {%0,%1,%2,%3};"
        : "+f"(d[0]), "+f"(d[1]), "+f"(d[2]), "+f"(d[3])
        : "r"(a[0]), "r"(a[1]), "r"(a[2]), "r"(a[3]), "r"(b[0]), "r"(b[1]));
}

// ------------------------- weight prep / init -------------------------------
__global__ void k_t1(const float* __restrict__ W1) {
    int i = blockIdx.x * 256 + threadIdx.x;
    int l = i / 16384, r = i - l * 16384;
    int n = r >> 6, k2 = r & 63;
    float w0 = W1[l * 32768 + (2 * k2) * 256 + n];
    float w1 = W1[l * 32768 + (2 * k2 + 1) * 256 + n];
    uint32_t hi, lo; split2(w0, w1, hi, lo);
    g_w1h[i] = hi; g_w1l[i] = lo;
}
__global__ void k_t2(const float* __restrict__ W2) {
    int i = blockIdx.x * 256 + threadIdx.x;
    int l = i / 16384, r = i - l * 16384;
    int n = r >> 7, k2 = r & 127;
    float w0 = W2[l * 32768 + (2 * k2) * 128 + n];
    float w1 = W2[l * 32768 + (2 * k2 + 1) * 128 + n];
    uint32_t hi, lo; split2(w0, w1, hi, lo);
    g_w2h[i] = hi; g_w2l[i] = lo;
}
__global__ void k_init(const int* __restrict__ x, const float* __restrict__ xe1, const float* __restrict__ xe2) {
    int t = blockIdx.x * 256 + threadIdx.x;
    int row = t >> 5, c4 = t & 31;
    int i0 = x[2 * row], i1 = x[2 * row + 1];
    float4 a = ((const float4*)xe1)[i0 * 32 + c4];
    float4 b = ((const float4*)xe2)[i1 * 32 + c4];
    ((float4*)g_h0)[t] = make_float4(a.x + b.x, a.y + b.y, a.z + b.z, a.w + b.w);
    if (blockIdx.x == 0 && threadIdx.x < 128) {
        g_sumsd[2 * threadIdx.x] = 0.0; g_sumsd[2 * threadIdx.x + 1] = 0.0;
    }
}

// ------------------------- CSR build ----------------------------------------
__global__ void k_ezero() { g_deg[blockIdx.x * 256 + threadIdx.x] = 0; }
__global__ void k_hist(const int* __restrict__ ei) {
    int e = blockIdx.x * 256 + threadIdx.x;
    atomicAdd(&g_deg[ei[NE + e]], 1);
}
__global__ void __launch_bounds__(1024) k_scan1() {
    __shared__ int s[1024];
    int t = threadIdx.x, i = blockIdx.x * 1024 + t;
    s[t] = g_deg[i];
    __syncthreads();
    #pragma unroll
    for (int off = 1; off < 1024; off <<= 1) {
        int x = (t >= off) ? s[t - off] : 0;
        __syncthreads();
        s[t] += x;
        __syncthreads();
    }
    g_rowptr[i + 1] = s[t];
    if (t == 1023) g_bsum[blockIdx.x] = s[1023];
}
__global__ void k_scan2() {
    __shared__ int s[128];
    int t = threadIdx.x;
    int v = g_bsum[t];
    s[t] = v;
    __syncthreads();
    #pragma unroll
    for (int off = 1; off < 128; off <<= 1) {
        int x = (t >= off) ? s[t - off] : 0;
        __syncthreads();
        s[t] += x;
        __syncthreads();
    }
    g_bsum[t] = s[t] - v;
}
__global__ void k_scan3() {
    int t = threadIdx.x, i = blockIdx.x * 256 + t;
    int base = g_bsum[i >> 10];
    int incl = g_rowptr[i + 1] + base;
    g_rowptr[i + 1] = incl;
    g_deg[i] = incl - g_deg[i];
    if (i == 0) g_rowptr[0] = 0;
}
__global__ void k_place(const int* __restrict__ ei, const int* __restrict__ ea) {
    int e = blockIdx.x * 256 + threadIdx.x;
    int dst = ei[NE + e];
    int src = ei[e];
    int combo = ea[2 * e] * 3 + ea[2 * e + 1];
    int pos = atomicAdd(&g_deg[dst], 1);
    g_eperm[pos] = src | (combo << 17);
}

// ------------------------- BN stats / final ---------------------------------
__global__ void k_stats(const float* __restrict__ gamma, const float* __restrict__ beta) {
    int c = threadIdx.x;
    double su = g_sumsd[c], sq = g_sumsd[128 + c];
    double mu  = su * (1.0 / NN);
    double var = sq * (1.0 / NN) - mu * mu;
    float sc = (float)(rsqrt(var + 1e-5) * (double)gamma[c]);
    g_ss[c] = sc;
    g_ss[128 + c] = (float)((double)beta[c] - mu * (double)sc);
    g_sumsd[c] = 0.0; g_sumsd[128 + c] = 0.0;          // ready for next layer
}
__global__ void k_final(float* __restrict__ out) {
    int t = blockIdx.x * 256 + threadIdx.x;
    int c4 = t & 31;
    float4 v = ((const float4*)g_bufA)[t];
    float4 s = ((const float4*)g_ss)[c4];
    float4 b = ((const float4*)g_ss)[32 + c4];
    ((float4*)out)[t] = make_float4(fmaf(v.x, s.x, b.x), fmaf(v.y, s.y, b.y),
                                    fmaf(v.z, s.z, b.z), fmaf(v.w, s.w, b.w));
}

// ------------------------- fused agg + MLP + BN sums ------------------------
// smem byte offsets (phase-exclusive overlays):
#define A1H_OFF 0           // 128 x 68 u32   (agg out hi)     [phase 1]
#define A1L_OFF 34816
#define B1H_OFF 69632       // 256 x 68 u32   (W1 full)        [phase 1]
#define B1L_OFF 139264      // ..208896
#define A2H_OFF 0           // 128 x 132 u32  (GEMM1 out hi)   [phase 2]
#define A2L_OFF 67584       // ..135168
#define A2_S    132
#define B2H_OFF 135168      // 128 x 20 u32   (W2 chunk)       [phase 2]
#define B2L_OFF 145408      // ..155648
#define SB_OFF  208896      // 384 floats
#define BND_OFF 210432      // 256 doubles
#define COMB_OFF 212480     // 18*32 float4
#define SM_TOT  221696

__global__ void __launch_bounds__(512, 1) k_fused(
    int src_sel, int dst_sel, const float* __restrict__ b1p, const float* __restrict__ b2p,
    int affine, int layer)
{
    extern __shared__ char smem[];
    uint32_t* A1H = (uint32_t*)(smem + A1H_OFF);
    uint32_t* A1L = (uint32_t*)(smem + A1L_OFF);
    uint32_t* A2H = (uint32_t*)(smem + A2H_OFF);
    uint32_t* A2L = (uint32_t*)(smem + A2L_OFF);
    uint32_t* B2H = (uint32_t*)(smem + B2H_OFF);
    uint32_t* B2L = (uint32_t*)(smem + B2L_OFF);
    float*    sb  = (float*)(smem + SB_OFF);
    double*   bnd = (double*)(smem + BND_OFF);
    float4*   comb = (float4*)(smem + COMB_OFF);
    const int tid = threadIdx.x, w = tid >> 5, lane = tid & 31;
    const int g = lane >> 2, tig = lane & 3;
    const int wm = w & 3, wn = w >> 2;
    const uint32_t* w1h = g_w1h + layer * 16384;
    const uint32_t* w1l = g_w1l + layer * 16384;
    const uint32_t* w2h = g_w2h + layer * 16384;
    const uint32_t* w2l = g_w2l + layer * 16384;
    const size_t rowbase = (size_t)blockIdx.x * 128;
    const float* hsrc = (src_sel == 0) ? g_h0 : (src_sel == 1 ? g_bufA : g_bufB);
    float* hout = (dst_sel == 1) ? g_bufA : g_bufB;

    // ---- issue cp.async of full W1 (overlaps aggregation) ----
    const uint32_t b1hS = sm2u(smem + B1H_OFF), b1lS = sm2u(smem + B1L_OFF);
    #pragma unroll
    for (int it = 0; it < 8; it++) {
        int i = it * 512 + tid, r = i >> 4, seg = (i & 15) * 4;
        CPASYNC16(b1hS + (r * 68 + seg) * 4, w1h + r * 64 + seg);
        CPASYNC16(b1lS + (r * 68 + seg) * 4, w1l + r * 64 + seg);
    }
    CPCOMMIT();

    // ---- small tables ----
    if (tid < 384) sb[tid] = (tid < 256) ? b1p[tid] : b2p[tid - 256];
    if (tid < 256) bnd[tid] = 0.0;
    {
        const float4* e1 = (const float4*)0;   // placeholder; comb built from g_ss-free tables below
    }
    __syncthreads();   // (comb filled below needs its own sync; see note)

    // NOTE: comb table passed via globals is rebuilt here each block (small).
    // e-embedding pointers are passed through constant params instead:
    // (see k_fused_launch wrapper: we stash them in __device__ pointers)
    // -- implemented via global pointers below --
    extern __device__ const float* g_e1ptr;
    extern __device__ const float* g_e2ptr;
    {
        const float4* e1 = (const float4*)g_e1ptr;
        const float4* e2 = (const float4*)g_e2ptr;
        for (int i = tid; i < 576; i += 512) {
            int cb = i >> 5, c4 = i & 31;
            int a0 = cb / 3, a1 = cb - a0 * 3;
            float4 v1 = e1[a0 * 32 + c4];
            float4 v2 = e2[a1 * 32 + c4];
            comb[i] = make_float4(v1.x + v2.x, v1.y + v2.y, v1.z + v2.z, v1.w + v2.w);
        }
    }
    __syncthreads();

    // ---- aggregation phase: warp w -> nodes rowbase + 8w .. +8 ----
    {
        float4 s4, h4;
        if (affine) { s4 = ((const float4*)g_ss)[lane]; h4 = ((const float4*)g_ss)[32 + lane]; }
        else { s4 = make_float4(1.f, 1.f, 1.f, 1.f); h4 = make_float4(0.f, 0.f, 0.f, 0.f); }
        const float4* src4 = (const float4*)hsrc;
        for (int j = 0; j < 8; j++) {
            int node = (int)rowbase + w * 8 + j;
            float4 v = src4[(size_t)node * 32 + lane];
            float4 acc;
            if (affine) {
                acc.x = fmaxf(fmaf(v.x, s4.x, h4.x), 0.f);
                acc.y = fmaxf(fmaf(v.y, s4.y, h4.y), 0.f);
                acc.z = fmaxf(fmaf(v.z, s4.z, h4.z), 0.f);
                acc.w = fmaxf(fmaf(v.w, s4.w, h4.w), 0.f);
            } else acc = v;
            float4 cm = comb[12 * 32 + lane];
            acc.x += cm.x; acc.y += cm.y; acc.z += cm.z; acc.w += cm.w;
            int beg = g_rowptr[node], end = g_rowptr[node + 1];
            int e = beg;
            for (; e + 1 < end; e += 2) {
                int p1 = g_eperm[e], p2 = g_eperm[e + 1];
                float4 u1 = src4[(size_t)(p1 & 0x1FFFF) * 32 + lane];
                float4 u2 = src4[(size_t)(p2 & 0x1FFFF) * 32 + lane];
                if (affine) {
                    u1.x = fmaxf(fmaf(u1.x, s4.x, h4.x), 0.f); u1.y = fmaxf(fmaf(u1.y, s4.y, h4.y), 0.f);
                    u1.z = fmaxf(fmaf(u1.z, s4.z, h4.z), 0.f); u1.w = fmaxf(fmaf(u1.w, s4.w, h4.w), 0.f);
                    u2.x = fmaxf(fmaf(u2.x, s4.x, h4.x), 0.f); u2.y = fmaxf(fmaf(u2.y, s4.y, h4.y), 0.f);
                    u2.z = fmaxf(fmaf(u2.z, s4.z, h4.z), 0.f); u2.w = fmaxf(fmaf(u2.w, s4.w, h4.w), 0.f);
                }
                float4 c1 = comb[(p1 >> 17) * 32 + lane];
                float4 c2 = comb[(p2 >> 17) * 32 + lane];
                acc.x += u1.x + c1.x + u2.x + c2.x;
                acc.y += u1.y + c1.y + u2.y + c2.y;
                acc.z += u1.z + c1.z + u2.z + c2.z;
                acc.w += u1.w + c1.w + u2.w + c2.w;
            }
            if (e < end) {
                int p = g_eperm[e];
                float4 u = src4[(size_t)(p & 0x1FFFF) * 32 + lane];
                if (affine) {
                    u.x = fmaxf(fmaf(u.x, s4.x, h4.x), 0.f); u.y = fmaxf(fmaf(u.y, s4.y, h4.y), 0.f);
                    u.z = fmaxf(fmaf(u.z, s4.z, h4.z), 0.f); u.w = fmaxf(fmaf(u.w, s4.w, h4.w), 0.f);
                }
                float4 c = comb[(p >> 17) * 32 + lane];
                acc.x += u.x + c.x; acc.y += u.y + c.y;
                acc.z += u.z + c.z; acc.w += u.w + c.w;
            }
            uint32_t hi0, lo0, hi1, lo1;
            split2(acc.x, acc.y, hi0, lo0);
            split2(acc.z, acc.w, hi1, lo1);
            int rl = w * 8 + j;
            *(uint2*)&A1H[rl * 68 + 2 * lane] = make_uint2(hi0, hi1);
            *(uint2*)&A1L[rl * 68 + 2 * lane] = make_uint2(lo0, lo1);
        }
    }
    CPWAIT0();
    __syncthreads();

    // ---- GEMM1: C1[128,256] = A1[128,128] @ W1^T, 8 straight K-steps ----
    const uint32_t a1hS = sm2u(A1H), a1lS = sm2u(A1L);
    const uint32_t a2hS = sm2u(A2H), a2lS = sm2u(A2L);
    const uint32_t b2hS = sm2u(B2H), b2lS = sm2u(B2L);
    const int lx = lane & 15, hx = lane >> 4;
    const int r7 = lane & 7, p8 = (lane >> 3) & 1, n8 = lane >> 4;
    const uint32_t offA1 = ((wm * 32 + lx) * 68 + hx * 4) * 4;
    const uint32_t offB1 = ((wn * 64 + n8 * 8 + r7) * 68 + p8 * 4) * 4;
    const uint32_t offA2 = ((wm * 32 + lx) * 132 + hx * 4) * 4;
    const uint32_t offB2 = ((wn * 32 + n8 * 8 + r7) * 20 + p8 * 4) * 4;

    float c1[2][8][4];
    #pragma unroll
    for (int mt = 0; mt < 2; mt++)
        #pragma unroll
        for (int nt = 0; nt < 8; nt++)
            #pragma unroll
            for (int q = 0; q < 4; q++) c1[mt][nt][q] = 0.f;

    #pragma unroll
    for (int s = 0; s < 8; s++) {
        const uint32_t kb = s * 32;
        uint32_t ah[2][4], al[2][4];
        LDSM4(ah[0][0], ah[0][1], ah[0][2], ah[0][3], a1hS + offA1 + kb);
        LDSM4(ah[1][0], ah[1][1], ah[1][2], ah[1][3], a1hS + offA1 + 4352 + kb);
        LDSM4(al[0][0], al[0][1], al[0][2], al[0][3], a1lS + offA1 + kb);
        LDSM4(al[1][0], al[1][1], al[1][2], al[1][3], a1lS + offA1 + 4352 + kb);
        #pragma unroll
        for (int np = 0; np < 4; np++) {
            uint32_t bh[4], bl[4];
            LDSM4(bh[0], bh[1], bh[2], bh[3], b1hS + offB1 + np * 4352 + kb);
            LDSM4(bl[0], bl[1], bl[2], bl[3], b1lS + offB1 + np * 4352 + kb);
            #pragma unroll
            for (int mt = 0; mt < 2; mt++) {
                mma_bf16(c1[mt][2 * np],     ah[mt], bh);
                mma_bf16(c1[mt][2 * np],     ah[mt], bl);
                mma_bf16(c1[mt][2 * np],     al[mt], bh);
                mma_bf16(c1[mt][2 * np + 1], ah[mt], bh + 2);
                mma_bf16(c1[mt][2 * np + 1], ah[mt], bl + 2);
                mma_bf16(c1[mt][2 * np + 1], al[mt], bh + 2);
            }
        }
    }
    __syncthreads();                                     // A1/B1 reads done

    // prefetch B2 chunk 0 while epilogue runs
    uint32_t qbh[4], qbl[4];
    #pragma unroll
    for (int it = 0; it < 4; it++) {
        int i = it * 512 + tid, r = i >> 4, p = i & 15;
        qbh[it] = w2h[r * 128 + p]; qbl[it] = w2l[r * 128 + p];
    }

    // epilogue1: +b1, relu, split -> A2
    #pragma unroll
    for (int mt = 0; mt < 2; mt++) {
        int r0 = wm * 32 + mt * 16 + g;
        #pragma unroll
        for (int nt = 0; nt < 8; nt++) {
            int cp = wn * 32 + nt * 4 + tig;
            float v0 = fmaxf(c1[mt][nt][0] + sb[2 * cp], 0.f);
            float v1 = fmaxf(c1[mt][nt][1] + sb[2 * cp + 1], 0.f);
            float v2 = fmaxf(c1[mt][nt][2] + sb[2 * cp], 0.f);
            float v3 = fmaxf(c1[mt][nt][3] + sb[2 * cp + 1], 0.f);
            uint32_t hi, lo;
            split2(v0, v1, hi, lo);
            A2H[r0 * A2_S + cp] = hi; A2L[r0 * A2_S + cp] = lo;
            split2(v2, v3, hi, lo);
            A2H[(r0 + 8) * A2_S + cp] = hi; A2L[(r0 + 8) * A2_S + cp] = lo;
        }
    }
    __syncthreads();

    // ---- GEMM2: C2[128,128] = A2[128,256] @ W2^T ----
    float c2[2][4][4];
    #pragma unroll
    for (int mt = 0; mt < 2; mt++)
        #pragma unroll
        for (int nt = 0; nt < 4; nt++)
            #pragma unroll
            for (int q = 0; q < 4; q++) c2[mt][nt][q] = 0.f;

    for (int kc = 0; kc < 8; kc++) {
        #pragma unroll
        for (int it = 0; it < 4; it++) {
            int i = it * 512 + tid, r = i >> 4, p = i & 15;
            B2H[r * 20 + p] = qbh[it]; B2L[r * 20 + p] = qbl[it];
        }
        __syncthreads();
        if (kc < 7) {
            #pragma unroll
            for (int it = 0; it < 4; it++) {
                int i = it * 512 + tid, r = i >> 4, p = i & 15;
                qbh[it] = w2h[r * 128 + (kc + 1) * 16 + p];
                qbl[it] = w2l[r * 128 + (kc + 1) * 16 + p];
            }
        }
        #pragma unroll
        for (int ks = 0; ks < 2; ks++) {
            const uint32_t kbA = (kc * 16 + ks * 8) * 4;
            const uint32_t kb4 = ks * 32;
            uint32_t ah[2][4], al[2][4];
            LDSM4(ah[0][0], ah[0][1], ah[0][2], ah[0][3], a2hS + offA2 + kbA);
            LDSM4(ah[1][0], ah[1][1], ah[1][2], ah[1][3], a2hS + offA2 + 8448 + kbA);
            LDSM4(al[0][0], al[0][1], al[0][2], al[0][3], a2lS + offA2 + kbA);
            LDSM4(al[1][0], al[1][1], al[1][2], al[1][3], a2lS + offA2 + 8448 + kbA);
            #pragma unroll
            for (int np = 0; np < 2; np++) {
                uint32_t bh[4], bl[4];
                LDSM4(bh[0], bh[1], bh[2], bh[3], b2hS + offB2 + np * 1280 + kb4);
                LDSM4(bl[0], bl[1], bl[2], bl[3], b2lS + offB2 + np * 1280 + kb4);
                #pragma unroll
                for (int mt = 0; mt < 2; mt++) {
                    mma_bf16(c2[mt][2 * np],     ah[mt], bh);
                    mma_bf16(c2[mt][2 * np],     ah[mt], bl);
                    mma_bf16(c2[mt][2 * np],     al[mt], bh);
                    mma_bf16(c2[mt][2 * np + 1], ah[mt], bh + 2);
                    mma_bf16(c2[mt][2 * np + 1], ah[mt], bl + 2);
                    mma_bf16(c2[mt][2 * np + 1], al[mt], bh + 2);
                }
            }
        }
        __syncthreads();
    }

    // epilogue2: +b2 -> hout, BN partial sums
    float* hm = hout + rowbase * DD;
    float sA[4][2], qA[4][2];
    #pragma unroll
    for (int nt = 0; nt < 4; nt++) { sA[nt][0] = sA[nt][1] = qA[nt][0] = qA[nt][1] = 0.f; }
    #pragma unroll
    for (int mt = 0; mt < 2; mt++) {
        int r0 = wm * 32 + mt * 16 + g;
        #pragma unroll
        for (int nt = 0; nt < 4; nt++) {
            int col = wn * 32 + nt * 8 + 2 * tig;
            float v00 = c2[mt][nt][0] + sb[256 + col];
            float v01 = c2[mt][nt][1] + sb[256 + col + 1];
            float v10 = c2[mt][nt][2] + sb[256 + col];
            float v11 = c2[mt][nt][3] + sb[256 + col + 1];
            *(float2*)&hm[r0 * DD + col] = make_float2(v00, v01);
            *(float2*)&hm[(r0 + 8) * DD + col] = make_float2(v10, v11);
            sA[nt][0] += v00 + v10; qA[nt][0] += v00 * v00 + v10 * v10;
            sA[nt][1] += v01 + v11; qA[nt][1] += v01 * v01 + v11 * v11;
        }
    }
    #pragma unroll
    for (int nt = 0; nt < 4; nt++)
        #pragma unroll
        for (int p = 0; p < 2; p++) {
            float s = sA[nt][p], q = qA[nt][p];
            #pragma unroll
            for (int o = 16; o >= 4; o >>= 1) {
                s += __shfl_xor_sync(0xFFFFFFFFu, s, o);
                q += __shfl_xor_sync(0xFFFFFFFFu, q, o);
            }
            if (g == 0) {
                int col = wn * 32 + nt * 8 + 2 * tig + p;
                atomicAdd(&bnd[col], (double)s);
                atomicAdd(&bnd[128 + col], (double)q);
            }
        }
    __syncthreads();
    if (tid < 256) atomicAdd(&g_sumsd[tid], bnd[tid]);
}

// e-embedding pointers for comb table (set per layer, graph-capturable memcpy)
__device__ const float* g_e1ptr;
__device__ const float* g_e2ptr;
__global__ void k_setptr(const float* e1, const float* e2) {
    g_e1ptr = e1; g_e2ptr = e2;
}

// ------------------------- launch -------------------------------------------
extern "C" void kernel_launch(void* const* d_in, const int* in_sizes, int n_in,
                              void* d_out, int out_size) {
    const int*   x    = (const int*)d_in[0];
    const int*   ei   = (const int*)d_in[1];
    const int*   ea   = (const int*)d_in[2];
    const float* xe1  = (const float*)d_in[3];
    const float* xe2  = (const float*)d_in[4];
    const float* ee1  = (const float*)d_in[5];
    const float* ee2  = (const float*)d_in[6];
    const float* W1   = (const float*)d_in[7];
    const float* b1   = (const float*)d_in[8];
    const float* W2   = (const float*)d_in[9];
    const float* b2   = (const float*)d_in[10];
    const float* gam  = (const float*)d_in[11];
    const float* bet  = (const float*)d_in[12];
    float* out = (float*)d_out;

    cudaFuncSetAttribute(k_fused, cudaFuncAttributeMaxDynamicSharedMemorySize, SM_TOT);

    k_t1<<<320, 256>>>(W1);
    k_t2<<<320, 256>>>(W2);
    k_init<<<16384, 256>>>(x, xe1, xe2);
    k_ezero<<<512, 256>>>();
    k_hist<<<1024, 256>>>(ei);
    k_scan1<<<128, 1024>>>();
    k_scan2<<<1, 128>>>();
    k_scan3<<<512, 256>>>();
    k_place<<<1024, 256>>>(ei, ea);

    static const int srcsel[LL] = {0, 1, 2, 1, 2};
    static const int dstsel[LL] = {1, 2, 1, 2, 1};
    for (int l = 0; l < LL; l++) {
        k_setptr<<<1, 1>>>(ee1 + (size_t)l * 6 * DD, ee2 + (size_t)l * 3 * DD);
        k_fused<<<1024, 512, SM_TOT>>>(srcsel[l], dstsel[l],
                                       b1 + l * 256, b2 + l * 128,
                                       l > 0 ? 1 : 0, l);
        k_stats<<<1, 128>>>(gam + l * DD, bet + l * DD);
    }
    k_final<<<16384, 256>>>(out);
}